// round 16
// baseline (speedup 1.0000x reference)
#include <cuda_runtime.h>
#include <cuda_bf16.h>

// bow_labeler: masked mean-pool over L, then 14 small linear heads (54 outputs).
// B=256, L=512, D=768.
// K0: memset g_sum (0.75 MB, captured memset node).
// K1: masked partial column sums; each block RED.ADDs its 192 float4 sums
//     directly into g_sum[b][:] (8 adds/address, hidden under the 38us
//     DRAM-bound stream). No partial buffer round-trip.
// K2: PDL epilogue, grid (64 batch-groups x 7 output-groups) x 256 thr:
//     pre-sync loads weights->registers + mask counts; post-sync reads the
//     tiny pooled sums (3 KB/block), normalizes, 54-head GEMV.

#define B_DIM   256
#define L_DIM   512
#define D_DIM   768
#define N_OUT   54
#define SPLIT   8
#define L_CHUNK (L_DIM / SPLIT)   // 64
#define D4      (D_DIM / 4)       // 192 float4 per row
#define T1      192
#define T3      256               // 8 warps
#define BPB     4                 // batches per epilogue block
#define NBG     (B_DIM / BPB)     // 64 batch groups
#define OGRP    7                 // output groups
#define OPG     8                 // outputs per group (last group: 6)

__device__ float g_sum[B_DIM * D_DIM];   // 0.75 MB accumulator (memset per launch)

__device__ __forceinline__ void f4acc(float4& a, const float4& v) {
    a.x += v.x; a.y += v.y; a.z += v.z; a.w += v.w;
}

// ---------------- K1: masked partial sums -> atomic accumulate ----------------
__global__ __launch_bounds__(T1) void pool_partial_kernel(
    const float* __restrict__ fh,
    const int*   __restrict__ mask)
{
    const int s  = blockIdx.x;
    const int b  = blockIdx.y;
    const int c4 = threadIdx.x;   // float4 column 0..191

    __shared__ int s_mask[L_CHUNK];
    if (c4 < L_CHUNK) s_mask[c4] = mask[b * L_DIM + s * L_CHUNK + c4];
    __syncthreads();

    const float4* base =
        (const float4*)(fh + ((size_t)b * L_DIM + (size_t)s * L_CHUNK) * D_DIM) + c4;

    float4 a0 = make_float4(0.f,0.f,0.f,0.f);
    float4 a1 = make_float4(0.f,0.f,0.f,0.f);
    float4 a2 = make_float4(0.f,0.f,0.f,0.f);
    float4 a3 = make_float4(0.f,0.f,0.f,0.f);
    #pragma unroll 1
    for (int l = 0; l < L_CHUNK; l += 8) {
        if (s_mask[l+0]) f4acc(a0, base[(size_t)(l+0) * D4]);
        if (s_mask[l+1]) f4acc(a1, base[(size_t)(l+1) * D4]);
        if (s_mask[l+2]) f4acc(a2, base[(size_t)(l+2) * D4]);
        if (s_mask[l+3]) f4acc(a3, base[(size_t)(l+3) * D4]);
        if (s_mask[l+4]) f4acc(a0, base[(size_t)(l+4) * D4]);
        if (s_mask[l+5]) f4acc(a1, base[(size_t)(l+5) * D4]);
        if (s_mask[l+6]) f4acc(a2, base[(size_t)(l+6) * D4]);
        if (s_mask[l+7]) f4acc(a3, base[(size_t)(l+7) * D4]);
    }
    f4acc(a0, a1); f4acc(a2, a3); f4acc(a0, a2);

    // Accumulate directly (RED.ADD.F32, no return). 8 adds per address total,
    // spread over the whole stream duration and all LTS slices.
    float* dst = g_sum + (size_t)b * D_DIM + c4 * 4;
    atomicAdd(dst + 0, a0.x);
    atomicAdd(dst + 1, a0.y);
    atomicAdd(dst + 2, a0.z);
    atomicAdd(dst + 3, a0.w);
}

// ---------------- K2: PDL epilogue (normalize + heads) ----------------
__global__ __launch_bounds__(T3) void epilogue_kernel(
    const int*   __restrict__ mask,
    const float* __restrict__ W13,
    const float* __restrict__ b13,
    const float* __restrict__ W14,
    const float* __restrict__ b14,
    float*       __restrict__ out)
{
    const int b0   = blockIdx.x * BPB;        // batch group
    const int og   = blockIdx.y;              // output group
    const int tid  = threadIdx.x;
    const int lane = tid & 31;
    const int warp = tid >> 5;                // 0..7

    __shared__ float4 s_pooled[BPB][D4];      // 12 KB
    __shared__ int    s_cnt[BPB];
    __shared__ float  s_inv[BPB];

    const int o       = og * OPG + warp;
    const bool active = (o < N_OUT);

    // ---- Pre-sync work (independent of K1, overlaps its tail) ----
    float4 w[D4 / 32];
    float  bias = 0.f;
    if (active) {
        const float4* w4 = (const float4*)((o < 52) ? (W13 + (size_t)o * D_DIM)
                                                    : (W14 + (size_t)(o - 52) * D_DIM));
        bias = (o < 52) ? b13[o] : b14[o - 52];
        #pragma unroll
        for (int i = 0; i < D4 / 32; i++) w[i] = w4[lane + 32 * i];
    }

    if (tid < BPB) s_cnt[tid] = 0;
    __syncthreads();
    #pragma unroll
    for (int bi = 0; bi < BPB; bi++) {
        const int* mrow = mask + (b0 + bi) * L_DIM;
        int m = mrow[tid] + mrow[tid + 256];
        #pragma unroll
        for (int off = 16; off; off >>= 1)
            m += __shfl_down_sync(0xffffffffu, m, off);
        if (lane == 0) atomicAdd(&s_cnt[bi], m);
    }
    __syncthreads();
    if (tid < BPB) s_inv[tid] = 1.0f / (float)s_cnt[tid];
    __syncthreads();

    // ---- Wait for K1 grid (all atomics complete at kernel boundary) ----
    cudaGridDependencySynchronize();

    // Read the 4 batches' summed vectors (3 KB/block) and normalize.
    #pragma unroll
    for (int k = 0; k < 3; k++) {
        int idx = tid + T3 * k;
        int bi = idx / D4, c4 = idx % D4;
        float4 cs = ((const float4*)(g_sum + (size_t)(b0 + bi) * D_DIM))[c4];
        float inv = s_inv[bi];
        cs.x *= inv; cs.y *= inv; cs.z *= inv; cs.w *= inv;
        s_pooled[bi][c4] = cs;
    }
    __syncthreads();

    if (!active) return;

    float acc[BPB] = {0.f, 0.f, 0.f, 0.f};
    #pragma unroll
    for (int i = 0; i < D4 / 32; i++) {
        #pragma unroll
        for (int bi = 0; bi < BPB; bi++) {
            float4 p = s_pooled[bi][lane + 32 * i];
            acc[bi] += w[i].x * p.x + w[i].y * p.y + w[i].z * p.z + w[i].w * p.w;
        }
    }
    #pragma unroll
    for (int off = 16; off; off >>= 1) {
        #pragma unroll
        for (int bi = 0; bi < BPB; bi++)
            acc[bi] += __shfl_down_sync(0xffffffffu, acc[bi], off);
    }
    if (lane == 0) {
        #pragma unroll
        for (int bi = 0; bi < BPB; bi++)
            out[(b0 + bi) * N_OUT + o] = acc[bi] + bias;
    }
}

extern "C" void kernel_launch(void* const* d_in, const int* in_sizes, int n_in,
                              void* d_out, int out_size)
{
    const float* fh   = (const float*)d_in[0];
    const int*   mask = (const int*)d_in[1];
    const float* W13  = (const float*)d_in[2];
    const float* b13  = (const float*)d_in[3];
    const float* W14  = (const float*)d_in[4];
    const float* b14  = (const float*)d_in[5];
    float* out = (float*)d_out;

    // Zero the accumulator (captured memset node; no allocation).
    void* sum_ptr = nullptr;
    cudaGetSymbolAddress(&sum_ptr, g_sum);
    cudaMemsetAsync(sum_ptr, 0, B_DIM * D_DIM * sizeof(float), 0);

    dim3 grid1(SPLIT, B_DIM);
    pool_partial_kernel<<<grid1, T1>>>(fh, mask);

    cudaLaunchAttribute attr[1];
    attr[0].id = cudaLaunchAttributeProgrammaticStreamSerialization;
    attr[0].val.programmaticStreamSerializationAllowed = 1;

    cudaLaunchConfig_t cfg = {};
    cfg.gridDim = dim3(NBG, OGRP);
    cfg.blockDim = dim3(T3);
    cfg.attrs = attr;
    cfg.numAttrs = 1;
    cudaLaunchKernelEx(&cfg, epilogue_kernel, mask, W13, b13, W14, b14, out);
}

// round 17
// speedup vs baseline: 1.0214x; 1.0214x over previous
#include <cuda_runtime.h>
#include <cuda_bf16.h>

// bow_labeler: masked mean-pool over L, then 14 small linear heads (54 outputs).
// B=256, L=512, D=768.
// K0: memset g_sum (0.75 MB, captured memset node).
// K1: masked partial column sums; RED.ADD into g_sum[b][:]. Calls
//     cudaTriggerProgrammaticLaunchCompletion() at block start so the PDL
//     epilogue actually launches early (missing in rounds 9-16!).
// K2: PDL epilogue, grid (64 batch-groups x 7 output-groups) x 256 thr:
//     pre-sync (overlapped with K1): weights->registers, mask counts;
//     post-sync: read pooled sums (3 KB/block), normalize, 54-head GEMV.

#define B_DIM   256
#define L_DIM   512
#define D_DIM   768
#define N_OUT   54
#define SPLIT   8
#define L_CHUNK (L_DIM / SPLIT)   // 64
#define D4      (D_DIM / 4)       // 192 float4 per row
#define T1      192
#define T3      256               // 8 warps
#define BPB     4                 // batches per epilogue block
#define NBG     (B_DIM / BPB)     // 64 batch groups
#define OGRP    7                 // output groups
#define OPG     8                 // outputs per group (last group: 6)

__device__ float g_sum[B_DIM * D_DIM];   // 0.75 MB accumulator (memset per launch)

__device__ __forceinline__ void f4acc(float4& a, const float4& v) {
    a.x += v.x; a.y += v.y; a.z += v.z; a.w += v.w;
}

// ---------------- K1: masked partial sums -> atomic accumulate ----------------
__global__ __launch_bounds__(T1) void pool_partial_kernel(
    const float* __restrict__ fh,
    const int*   __restrict__ mask)
{
    // Signal PDL: allow the dependent epilogue grid to launch as soon as all
    // K1 blocks have started (its pre-sync work then overlaps this stream).
    cudaTriggerProgrammaticLaunchCompletion();

    const int s  = blockIdx.x;
    const int b  = blockIdx.y;
    const int c4 = threadIdx.x;   // float4 column 0..191

    __shared__ int s_mask[L_CHUNK];
    if (c4 < L_CHUNK) s_mask[c4] = mask[b * L_DIM + s * L_CHUNK + c4];
    __syncthreads();

    const float4* base =
        (const float4*)(fh + ((size_t)b * L_DIM + (size_t)s * L_CHUNK) * D_DIM) + c4;

    float4 a0 = make_float4(0.f,0.f,0.f,0.f);
    float4 a1 = make_float4(0.f,0.f,0.f,0.f);
    float4 a2 = make_float4(0.f,0.f,0.f,0.f);
    float4 a3 = make_float4(0.f,0.f,0.f,0.f);
    #pragma unroll 1
    for (int l = 0; l < L_CHUNK; l += 8) {
        if (s_mask[l+0]) f4acc(a0, base[(size_t)(l+0) * D4]);
        if (s_mask[l+1]) f4acc(a1, base[(size_t)(l+1) * D4]);
        if (s_mask[l+2]) f4acc(a2, base[(size_t)(l+2) * D4]);
        if (s_mask[l+3]) f4acc(a3, base[(size_t)(l+3) * D4]);
        if (s_mask[l+4]) f4acc(a0, base[(size_t)(l+4) * D4]);
        if (s_mask[l+5]) f4acc(a1, base[(size_t)(l+5) * D4]);
        if (s_mask[l+6]) f4acc(a2, base[(size_t)(l+6) * D4]);
        if (s_mask[l+7]) f4acc(a3, base[(size_t)(l+7) * D4]);
    }
    f4acc(a0, a1); f4acc(a2, a3); f4acc(a0, a2);

    // RED.ADD.F32, no return; 8 adds/address spread over the whole stream.
    float* dst = g_sum + (size_t)b * D_DIM + c4 * 4;
    atomicAdd(dst + 0, a0.x);
    atomicAdd(dst + 1, a0.y);
    atomicAdd(dst + 2, a0.z);
    atomicAdd(dst + 3, a0.w);
}

// ---------------- K2: PDL epilogue (normalize + heads) ----------------
__global__ __launch_bounds__(T3) void epilogue_kernel(
    const int*   __restrict__ mask,
    const float* __restrict__ W13,
    const float* __restrict__ b13,
    const float* __restrict__ W14,
    const float* __restrict__ b14,
    float*       __restrict__ out)
{
    const int b0   = blockIdx.x * BPB;        // batch group
    const int og   = blockIdx.y;              // output group
    const int tid  = threadIdx.x;
    const int lane = tid & 31;
    const int warp = tid >> 5;                // 0..7

    __shared__ float4 s_pooled[BPB][D4];      // 12 KB
    __shared__ int    s_cnt[BPB];
    __shared__ float  s_inv[BPB];

    const int o       = og * OPG + warp;
    const bool active = (o < N_OUT);

    // ---- Pre-sync work (now genuinely overlapped with K1's stream) ----
    float4 w[D4 / 32];
    float  bias = 0.f;
    if (active) {
        const float4* w4 = (const float4*)((o < 52) ? (W13 + (size_t)o * D_DIM)
                                                    : (W14 + (size_t)(o - 52) * D_DIM));
        bias = (o < 52) ? b13[o] : b14[o - 52];
        #pragma unroll
        for (int i = 0; i < D4 / 32; i++) w[i] = w4[lane + 32 * i];
    }

    if (tid < BPB) s_cnt[tid] = 0;
    __syncthreads();
    #pragma unroll
    for (int bi = 0; bi < BPB; bi++) {
        const int* mrow = mask + (b0 + bi) * L_DIM;
        int m = mrow[tid] + mrow[tid + 256];
        #pragma unroll
        for (int off = 16; off; off >>= 1)
            m += __shfl_down_sync(0xffffffffu, m, off);
        if (lane == 0) atomicAdd(&s_cnt[bi], m);
    }
    __syncthreads();
    if (tid < BPB) s_inv[tid] = 1.0f / (float)s_cnt[tid];
    __syncthreads();

    // ---- Wait for K1 grid (HW sleep until all K1 memory ops visible) ----
    cudaGridDependencySynchronize();

    // Read the 4 batches' summed vectors (3 KB/block) and normalize.
    #pragma unroll
    for (int k = 0; k < 3; k++) {
        int idx = tid + T3 * k;
        int bi = idx / D4, c4 = idx % D4;
        float4 cs = ((const float4*)(g_sum + (size_t)(b0 + bi) * D_DIM))[c4];
        float inv = s_inv[bi];
        cs.x *= inv; cs.y *= inv; cs.z *= inv; cs.w *= inv;
        s_pooled[bi][c4] = cs;
    }
    __syncthreads();

    if (!active) return;

    float acc[BPB] = {0.f, 0.f, 0.f, 0.f};
    #pragma unroll
    for (int i = 0; i < D4 / 32; i++) {
        #pragma unroll
        for (int bi = 0; bi < BPB; bi++) {
            float4 p = s_pooled[bi][lane + 32 * i];
            acc[bi] += w[i].x * p.x + w[i].y * p.y + w[i].z * p.z + w[i].w * p.w;
        }
    }
    #pragma unroll
    for (int off = 16; off; off >>= 1) {
        #pragma unroll
        for (int bi = 0; bi < BPB; bi++)
            acc[bi] += __shfl_down_sync(0xffffffffu, acc[bi], off);
    }
    if (lane == 0) {
        #pragma unroll
        for (int bi = 0; bi < BPB; bi++)
            out[(b0 + bi) * N_OUT + o] = acc[bi] + bias;
    }
}

extern "C" void kernel_launch(void* const* d_in, const int* in_sizes, int n_in,
                              void* d_out, int out_size)
{
    const float* fh   = (const float*)d_in[0];
    const int*   mask = (const int*)d_in[1];
    const float* W13  = (const float*)d_in[2];
    const float* b13  = (const float*)d_in[3];
    const float* W14  = (const float*)d_in[4];
    const float* b14  = (const float*)d_in[5];
    float* out = (float*)d_out;

    // Zero the accumulator (captured memset node; no allocation).
    void* sum_ptr = nullptr;
    cudaGetSymbolAddress(&sum_ptr, g_sum);
    cudaMemsetAsync(sum_ptr, 0, B_DIM * D_DIM * sizeof(float), 0);

    dim3 grid1(SPLIT, B_DIM);
    pool_partial_kernel<<<grid1, T1>>>(fh, mask);

    cudaLaunchAttribute attr[1];
    attr[0].id = cudaLaunchAttributeProgrammaticStreamSerialization;
    attr[0].val.programmaticStreamSerializationAllowed = 1;

    cudaLaunchConfig_t cfg = {};
    cfg.gridDim = dim3(NBG, OGRP);
    cfg.blockDim = dim3(T3);
    cfg.attrs = attr;
    cfg.numAttrs = 1;
    cudaLaunchKernelEx(&cfg, epilogue_kernel, mask, W13, b13, W14, b14, out);
}